// round 2
// baseline (speedup 1.0000x reference)
#include <cuda_runtime.h>

#define TILE 128
#define NTHREADS 256
#define WARPS 8
#define ROWS_PER_WARP (TILE / WARPS)   // 16
#define GROUPS (ROWS_PER_WARP / 4)     // 4
#define PI_F 3.14159265358979323846f
#define RSQRT2 0.70710678118654752440f

__global__ __launch_bounds__(NTHREADS) void qp_kernel(
    const float* __restrict__ x,       // [B,1024]
    const float* __restrict__ pre_w,   // [4,1024]
    const float* __restrict__ pre_b,   // [4]
    const float* __restrict__ qw,      // [1,4,3]
    const float* __restrict__ post_w,  // [1024,4]
    const float* __restrict__ post_b,  // [1024]
    float* __restrict__ out,           // [B,1024]
    int B)
{
    __shared__ float wsm[4][1024];     // pre_w, q-major
    __shared__ float psm[4][1024];     // post_w SoA: psm[q][j]
    __shared__ float pbsm[1024];       // post_b
    __shared__ float usm[4][8];        // Rot gate matrices (uniform)

    const int tid  = threadIdx.x;
    const int warp = tid >> 5;
    const int lane = tid & 31;
    const int tile0 = blockIdx.x * TILE;

    // ---------------- stage weights into SMEM (once) ----------------
    for (int i = tid; i < 4096; i += NTHREADS)
        ((float*)wsm)[i] = pre_w[i];

    const float4* pwg4 = (const float4*)post_w;   // [1024] float4, (j, q=0..3)
    for (int j = tid; j < 1024; j += NTHREADS) {
        float4 v = pwg4[j];
        psm[0][j] = v.x; psm[1][j] = v.y; psm[2][j] = v.z; psm[3][j] = v.w;
        pbsm[j] = post_b[j];
    }
    if (tid < 4) {
        float phi = qw[tid * 3 + 0];
        float th  = qw[tid * 3 + 1];
        float om  = qw[tid * 3 + 2];
        float spo, cpo, spm, cpm, st, ct;
        sincosf(0.5f * (phi + om), &spo, &cpo);
        sincosf(0.5f * (phi - om), &spm, &cpm);
        sincosf(0.5f * th,         &st,  &ct);
        usm[tid][0] =  cpo * ct;  usm[tid][1] = -spo * ct;  // u00
        usm[tid][2] = -cpm * st;  usm[tid][3] = -spm * st;  // u01
        usm[tid][4] =  cpm * st;  usm[tid][5] = -spm * st;  // u10
        usm[tid][6] =  cpo * ct;  usm[tid][7] =  spo * ct;  // u11
    }
    // per-thread copy of pre_b (broadcast L1/L2 hit)
    const float pb0 = __ldg(&pre_b[0]);
    const float pb1 = __ldg(&pre_b[1]);
    const float pb2 = __ldg(&pre_b[2]);
    const float pb3 = __ldg(&pre_b[3]);
    __syncthreads();

    // ---------------- warp-autonomous main loop over 4-row groups ----------
    #pragma unroll 1
    for (int g = 0; g < GROUPS; g++) {
        const int r0 = tile0 + warp * ROWS_PER_WARP + g * 4;   // global row base
        if (r0 + 3 >= B) continue;

        // ---- dots: acc[r][q] = x[r] . pre_w[q]  (partial per lane) ----
        const float4* xr0 = (const float4*)(x + (size_t)r0 * 1024);
        float acc[4][4];
        #pragma unroll
        for (int r = 0; r < 4; r++)
            #pragma unroll
            for (int q = 0; q < 4; q++) acc[r][q] = 0.0f;

        #pragma unroll
        for (int it = 0; it < 8; it++) {
            const int idx = it * 32 + lane;
            float4 w0 = ((const float4*)wsm[0])[idx];
            float4 w1 = ((const float4*)wsm[1])[idx];
            float4 w2 = ((const float4*)wsm[2])[idx];
            float4 w3 = ((const float4*)wsm[3])[idx];
            #pragma unroll
            for (int r = 0; r < 4; r++) {
                float4 xv = __ldcs(&xr0[(size_t)r * 256 + idx]);
                acc[r][0] += xv.x*w0.x + xv.y*w0.y + xv.z*w0.z + xv.w*w0.w;
                acc[r][1] += xv.x*w1.x + xv.y*w1.y + xv.z*w1.z + xv.w*w1.w;
                acc[r][2] += xv.x*w2.x + xv.y*w2.y + xv.z*w2.z + xv.w*w2.w;
                acc[r][3] += xv.x*w3.x + xv.y*w3.y + xv.z*w3.z + xv.w*w3.w;
            }
        }
        // butterfly reduce — every lane ends with full sums
        #pragma unroll
        for (int r = 0; r < 4; r++)
            #pragma unroll
            for (int q = 0; q < 4; q++)
                #pragma unroll
                for (int off = 16; off > 0; off >>= 1)
                    acc[r][q] += __shfl_xor_sync(0xffffffffu, acc[r][q], off);

        // ---- circuit: lanes 0..3 each simulate one row ----
        float z0 = 0.f, z1 = 0.f, z2 = 0.f, z3 = 0.f;
        if (lane < 4) {
            float hq[4];
            hq[0] = tanhf(acc[lane][0] + pb0) * PI_F;
            hq[1] = tanhf(acc[lane][1] + pb1) * PI_F;
            hq[2] = tanhf(acc[lane][2] + pb2) * PI_F;
            hq[3] = tanhf(acc[lane][3] + pb3) * PI_F;

            // v_q = RZ(atan(f^2)) RY(atan(f)) H |0>
            float vr[4][2], vi[4][2];
            #pragma unroll
            for (int q = 0; q < 4; q++) {
                float f = hq[q];
                float sa, ca; sincosf(0.5f * atanf(f), &sa, &ca);
                float A  = (ca - sa) * RSQRT2;
                float Bv = (ca + sa) * RSQRT2;
                float sb, cb; sincosf(0.5f * atanf(f * f), &sb, &cb);
                vr[q][0] = A  * cb;  vi[q][0] = -A  * sb;
                vr[q][1] = Bv * cb;  vi[q][1] =  Bv * sb;
            }
            // product state: qubit q <-> index bit (3-q)
            float c2r[4], c2i[4];
            #pragma unroll
            for (int j = 0; j < 4; j++) {
                int b3 = (j >> 1) & 1, b2 = j & 1;
                c2r[j] = vr[0][b3]*vr[1][b2] - vi[0][b3]*vi[1][b2];
                c2i[j] = vr[0][b3]*vi[1][b2] + vi[0][b3]*vr[1][b2];
            }
            float c3r[8], c3i[8];
            #pragma unroll
            for (int j = 0; j < 8; j++) {
                int hi = j >> 1, b1 = j & 1;
                c3r[j] = c2r[hi]*vr[2][b1] - c2i[hi]*vi[2][b1];
                c3i[j] = c2r[hi]*vi[2][b1] + c2i[hi]*vr[2][b1];
            }
            float pr[16], pim[16];
            #pragma unroll
            for (int j = 0; j < 16; j++) {
                int hi = j >> 1, b0 = j & 1;
                pr[j]  = c3r[hi]*vr[3][b0] - c3i[hi]*vi[3][b0];
                pim[j] = c3r[hi]*vi[3][b0] + c3i[hi]*vr[3][b0];
            }
            // CNOT ring composed into one compile-time gather permutation
            float tr[16], ti[16];
            #pragma unroll
            for (int j = 0; j < 16; j++) {
                int xg = j;
                xg ^= (xg & 1) << 3;           // CNOT c=3,t=0
                xg ^= (xg >> 1) & 1;           // CNOT c=2,t=3
                xg ^= ((xg >> 2) & 1) << 1;    // CNOT c=1,t=2
                xg ^= ((xg >> 3) & 1) << 2;    // CNOT c=0,t=1
                tr[j] = pr[xg];
                ti[j] = pim[xg];
            }
            // Rot gates (uniform matrices from SMEM), wire q -> bit (3-q)
            #pragma unroll
            for (int q = 0; q < 4; q++) {
                const float u00r = usm[q][0], u00i = usm[q][1];
                const float u01r = usm[q][2], u01i = usm[q][3];
                const float u10r = usm[q][4], u10i = usm[q][5];
                const float u11r = usm[q][6], u11i = usm[q][7];
                const int mask = 8 >> q;
                #pragma unroll
                for (int j0 = 0; j0 < 16; j0++) {
                    if (j0 & mask) continue;
                    const int j1 = j0 | mask;
                    float ar = tr[j0], ai = ti[j0];
                    float br = tr[j1], bi = ti[j1];
                    tr[j0] = u00r*ar - u00i*ai + u01r*br - u01i*bi;
                    ti[j0] = u00r*ai + u00i*ar + u01r*bi + u01i*br;
                    tr[j1] = u10r*ar - u10i*ai + u11r*br - u11i*bi;
                    ti[j1] = u10r*ai + u10i*ar + u11r*bi + u11i*br;
                }
            }
            // z_q = sum_j |psi_j|^2 * (1 - 2*bit_{3-q}(j))
            #pragma unroll
            for (int j = 0; j < 16; j++) {
                float p = tr[j]*tr[j] + ti[j]*ti[j];
                z0 += (j & 8) ? -p : p;
                z1 += (j & 4) ? -p : p;
                z2 += (j & 2) ? -p : p;
                z3 += (j & 1) ? -p : p;
            }
        }

        // ---- broadcast z-vectors of rows 0..3 (held on lanes 0..3) ----
        float4 zv0, zv1, zv2, zv3;
        zv0.x = __shfl_sync(0xffffffffu, z0, 0);
        zv0.y = __shfl_sync(0xffffffffu, z1, 0);
        zv0.z = __shfl_sync(0xffffffffu, z2, 0);
        zv0.w = __shfl_sync(0xffffffffu, z3, 0);
        zv1.x = __shfl_sync(0xffffffffu, z0, 1);
        zv1.y = __shfl_sync(0xffffffffu, z1, 1);
        zv1.z = __shfl_sync(0xffffffffu, z2, 1);
        zv1.w = __shfl_sync(0xffffffffu, z3, 1);
        zv2.x = __shfl_sync(0xffffffffu, z0, 2);
        zv2.y = __shfl_sync(0xffffffffu, z1, 2);
        zv2.z = __shfl_sync(0xffffffffu, z2, 2);
        zv2.w = __shfl_sync(0xffffffffu, z3, 2);
        zv3.x = __shfl_sync(0xffffffffu, z0, 3);
        zv3.y = __shfl_sync(0xffffffffu, z1, 3);
        zv3.z = __shfl_sync(0xffffffffu, z2, 3);
        zv3.w = __shfl_sync(0xffffffffu, z3, 3);

        // ---- stores: out[r] = z[r] @ post_w^T + post_b ----
        float4* o0 = (float4*)(out + (size_t)r0 * 1024);
        #pragma unroll
        for (int jt = 0; jt < 8; jt++) {
            const int fi = jt * 32 + lane;
            float4 w0 = ((const float4*)psm[0])[fi];
            float4 w1 = ((const float4*)psm[1])[fi];
            float4 w2 = ((const float4*)psm[2])[fi];
            float4 w3 = ((const float4*)psm[3])[fi];
            float4 bb = ((const float4*)pbsm)[fi];
            float4 o;
            o.x = bb.x + zv0.x*w0.x + zv0.y*w1.x + zv0.z*w2.x + zv0.w*w3.x;
            o.y = bb.y + zv0.x*w0.y + zv0.y*w1.y + zv0.z*w2.y + zv0.w*w3.y;
            o.z = bb.z + zv0.x*w0.z + zv0.y*w1.z + zv0.z*w2.z + zv0.w*w3.z;
            o.w = bb.w + zv0.x*w0.w + zv0.y*w1.w + zv0.z*w2.w + zv0.w*w3.w;
            __stcs(&o0[fi], o);
            o.x = bb.x + zv1.x*w0.x + zv1.y*w1.x + zv1.z*w2.x + zv1.w*w3.x;
            o.y = bb.y + zv1.x*w0.y + zv1.y*w1.y + zv1.z*w2.y + zv1.w*w3.y;
            o.z = bb.z + zv1.x*w0.z + zv1.y*w1.z + zv1.z*w2.z + zv1.w*w3.z;
            o.w = bb.w + zv1.x*w0.w + zv1.y*w1.w + zv1.z*w2.w + zv1.w*w3.w;
            __stcs(&o0[256 + fi], o);
            o.x = bb.x + zv2.x*w0.x + zv2.y*w1.x + zv2.z*w2.x + zv2.w*w3.x;
            o.y = bb.y + zv2.x*w0.y + zv2.y*w1.y + zv2.z*w2.y + zv2.w*w3.y;
            o.z = bb.z + zv2.x*w0.z + zv2.y*w1.z + zv2.z*w2.z + zv2.w*w3.z;
            o.w = bb.w + zv2.x*w0.w + zv2.y*w1.w + zv2.z*w2.w + zv2.w*w3.w;
            __stcs(&o0[512 + fi], o);
            o.x = bb.x + zv3.x*w0.x + zv3.y*w1.x + zv3.z*w2.x + zv3.w*w3.x;
            o.y = bb.y + zv3.x*w0.y + zv3.y*w1.y + zv3.z*w2.y + zv3.w*w3.y;
            o.z = bb.z + zv3.x*w0.z + zv3.y*w1.z + zv3.z*w2.z + zv3.w*w3.z;
            o.w = bb.w + zv3.x*w0.w + zv3.y*w1.w + zv3.z*w2.w + zv3.w*w3.w;
            __stcs(&o0[768 + fi], o);
        }
    }
}

extern "C" void kernel_launch(void* const* d_in, const int* in_sizes, int n_in,
                              void* d_out, int out_size) {
    const float* x      = (const float*)d_in[0];
    const float* pre_w  = (const float*)d_in[1];
    const float* pre_b  = (const float*)d_in[2];
    const float* qw     = (const float*)d_in[3];
    const float* post_w = (const float*)d_in[4];
    const float* post_b = (const float*)d_in[5];
    float* out = (float*)d_out;

    const int B = in_sizes[0] / 1024;
    const int blocks = (B + TILE - 1) / TILE;
    qp_kernel<<<blocks, NTHREADS>>>(x, pre_w, pre_b, qw, post_w, post_b, out, B);
}

// round 3
// speedup vs baseline: 1.1688x; 1.1688x over previous
#include <cuda_runtime.h>

#define TILE 128
#define NTHREADS 256
#define WARPS 8
#define ROWS_PER_WARP (TILE / WARPS)   // 16
#define GROUPS (ROWS_PER_WARP / 4)     // 4
#define PI_F 3.14159265358979323846f
#define RSQRT2 0.70710678118654752440f
#define BMAX 65536

__device__ float4 g_s[BMAX];   // raw dot products per row
__device__ float4 g_z[BMAX];   // circuit expectation values per row

// ======================= Kernel A: s = x @ pre_w^T =======================
__global__ __launch_bounds__(NTHREADS, 5) void dots_kernel(
    const float* __restrict__ x,       // [B,1024]
    const float* __restrict__ pre_w,   // [4,1024]
    int B)
{
    __shared__ float wsm[4][1024];

    const int tid  = threadIdx.x;
    const int warp = tid >> 5;
    const int lane = tid & 31;
    const int tile0 = blockIdx.x * TILE;

    for (int i = tid; i < 4096; i += NTHREADS)
        ((float*)wsm)[i] = pre_w[i];
    __syncthreads();

    #pragma unroll 1
    for (int g = 0; g < GROUPS; g++) {
        const int r0 = tile0 + warp * ROWS_PER_WARP + g * 4;
        if (r0 + 3 >= B) continue;

        const float4* xr0 = (const float4*)(x + (size_t)r0 * 1024);
        float acc[4][4];
        #pragma unroll
        for (int r = 0; r < 4; r++)
            #pragma unroll
            for (int q = 0; q < 4; q++) acc[r][q] = 0.0f;

        #pragma unroll
        for (int it = 0; it < 8; it++) {
            const int idx = it * 32 + lane;
            float4 w0 = ((const float4*)wsm[0])[idx];
            float4 w1 = ((const float4*)wsm[1])[idx];
            float4 w2 = ((const float4*)wsm[2])[idx];
            float4 w3 = ((const float4*)wsm[3])[idx];
            #pragma unroll
            for (int r = 0; r < 4; r++) {
                float4 xv = __ldcs(&xr0[(size_t)r * 256 + idx]);
                acc[r][0] += xv.x*w0.x + xv.y*w0.y + xv.z*w0.z + xv.w*w0.w;
                acc[r][1] += xv.x*w1.x + xv.y*w1.y + xv.z*w1.z + xv.w*w1.w;
                acc[r][2] += xv.x*w2.x + xv.y*w2.y + xv.z*w2.z + xv.w*w2.w;
                acc[r][3] += xv.x*w3.x + xv.y*w3.y + xv.z*w3.z + xv.w*w3.w;
            }
        }
        #pragma unroll
        for (int r = 0; r < 4; r++)
            #pragma unroll
            for (int q = 0; q < 4; q++)
                #pragma unroll
                for (int off = 16; off > 0; off >>= 1)
                    acc[r][q] += __shfl_xor_sync(0xffffffffu, acc[r][q], off);

        if (lane < 4)
            g_s[r0 + lane] = make_float4(acc[lane][0], acc[lane][1],
                                         acc[lane][2], acc[lane][3]);
    }
}

// ======================= Kernel C: z = circuit(tanh(s+b)*pi) =============
__global__ __launch_bounds__(NTHREADS) void circuit_kernel(
    const float* __restrict__ pre_b,   // [4]
    const float* __restrict__ qw,      // [1,4,3]
    int B)
{
    __shared__ float usm[4][8];
    const int tid = threadIdx.x;

    if (tid < 4) {
        float phi = qw[tid * 3 + 0];
        float th  = qw[tid * 3 + 1];
        float om  = qw[tid * 3 + 2];
        float spo, cpo, spm, cpm, st, ct;
        sincosf(0.5f * (phi + om), &spo, &cpo);
        sincosf(0.5f * (phi - om), &spm, &cpm);
        sincosf(0.5f * th,         &st,  &ct);
        usm[tid][0] =  cpo * ct;  usm[tid][1] = -spo * ct;  // u00
        usm[tid][2] = -cpm * st;  usm[tid][3] = -spm * st;  // u01
        usm[tid][4] =  cpm * st;  usm[tid][5] = -spm * st;  // u10
        usm[tid][6] =  cpo * ct;  usm[tid][7] =  spo * ct;  // u11
    }
    const float pb0 = __ldg(&pre_b[0]);
    const float pb1 = __ldg(&pre_b[1]);
    const float pb2 = __ldg(&pre_b[2]);
    const float pb3 = __ldg(&pre_b[3]);
    __syncthreads();

    const int r = blockIdx.x * NTHREADS + tid;
    if (r >= B) return;

    float4 sv = g_s[r];
    float hq[4];
    hq[0] = tanhf(sv.x + pb0) * PI_F;
    hq[1] = tanhf(sv.y + pb1) * PI_F;
    hq[2] = tanhf(sv.z + pb2) * PI_F;
    hq[3] = tanhf(sv.w + pb3) * PI_F;

    // v_q = RZ(atan(f^2)) RY(atan(f)) H |0>
    float vr[4][2], vi[4][2];
    #pragma unroll
    for (int q = 0; q < 4; q++) {
        float f = hq[q];
        float sa, ca; sincosf(0.5f * atanf(f), &sa, &ca);
        float A  = (ca - sa) * RSQRT2;
        float Bv = (ca + sa) * RSQRT2;
        float sb, cb; sincosf(0.5f * atanf(f * f), &sb, &cb);
        vr[q][0] = A  * cb;  vi[q][0] = -A  * sb;
        vr[q][1] = Bv * cb;  vi[q][1] =  Bv * sb;
    }
    // product state: qubit q <-> index bit (3-q)
    float c2r[4], c2i[4];
    #pragma unroll
    for (int j = 0; j < 4; j++) {
        int b3 = (j >> 1) & 1, b2 = j & 1;
        c2r[j] = vr[0][b3]*vr[1][b2] - vi[0][b3]*vi[1][b2];
        c2i[j] = vr[0][b3]*vi[1][b2] + vi[0][b3]*vr[1][b2];
    }
    float c3r[8], c3i[8];
    #pragma unroll
    for (int j = 0; j < 8; j++) {
        int hi = j >> 1, b1 = j & 1;
        c3r[j] = c2r[hi]*vr[2][b1] - c2i[hi]*vi[2][b1];
        c3i[j] = c2r[hi]*vi[2][b1] + c2i[hi]*vr[2][b1];
    }
    float pr[16], pim[16];
    #pragma unroll
    for (int j = 0; j < 16; j++) {
        int hi = j >> 1, b0 = j & 1;
        pr[j]  = c3r[hi]*vr[3][b0] - c3i[hi]*vi[3][b0];
        pim[j] = c3r[hi]*vi[3][b0] + c3i[hi]*vr[3][b0];
    }
    // CNOT ring composed into one compile-time gather permutation
    float tr[16], ti[16];
    #pragma unroll
    for (int j = 0; j < 16; j++) {
        int xg = j;
        xg ^= (xg & 1) << 3;           // CNOT c=3,t=0
        xg ^= (xg >> 1) & 1;           // CNOT c=2,t=3
        xg ^= ((xg >> 2) & 1) << 1;    // CNOT c=1,t=2
        xg ^= ((xg >> 3) & 1) << 2;    // CNOT c=0,t=1
        tr[j] = pr[xg];
        ti[j] = pim[xg];
    }
    // Rot gates (uniform matrices from SMEM), wire q -> bit (3-q)
    #pragma unroll
    for (int q = 0; q < 4; q++) {
        const float u00r = usm[q][0], u00i = usm[q][1];
        const float u01r = usm[q][2], u01i = usm[q][3];
        const float u10r = usm[q][4], u10i = usm[q][5];
        const float u11r = usm[q][6], u11i = usm[q][7];
        const int mask = 8 >> q;
        #pragma unroll
        for (int j0 = 0; j0 < 16; j0++) {
            if (j0 & mask) continue;
            const int j1 = j0 | mask;
            float ar = tr[j0], ai = ti[j0];
            float br = tr[j1], bi = ti[j1];
            tr[j0] = u00r*ar - u00i*ai + u01r*br - u01i*bi;
            ti[j0] = u00r*ai + u00i*ar + u01r*bi + u01i*br;
            tr[j1] = u10r*ar - u10i*ai + u11r*br - u11i*bi;
            ti[j1] = u10r*ai + u10i*ar + u11r*bi + u11i*br;
        }
    }
    // z_q = sum_j |psi_j|^2 * (1 - 2*bit_{3-q}(j))
    float z0 = 0.f, z1 = 0.f, z2 = 0.f, z3 = 0.f;
    #pragma unroll
    for (int j = 0; j < 16; j++) {
        float p = tr[j]*tr[j] + ti[j]*ti[j];
        z0 += (j & 8) ? -p : p;
        z1 += (j & 4) ? -p : p;
        z2 += (j & 2) ? -p : p;
        z3 += (j & 1) ? -p : p;
    }
    g_z[r] = make_float4(z0, z1, z2, z3);
}

// ======================= Kernel B: out = z @ post_w^T + post_b ===========
__global__ __launch_bounds__(NTHREADS) void post_kernel(
    const float* __restrict__ post_w,  // [1024,4]
    const float* __restrict__ post_b,  // [1024]
    float* __restrict__ out,           // [B,1024]
    int B)
{
    __shared__ float psm[4][1024];
    __shared__ float pbsm[1024];

    const int tid  = threadIdx.x;
    const int warp = tid >> 5;
    const int lane = tid & 31;
    const int tile0 = blockIdx.x * TILE;

    const float4* pwg4 = (const float4*)post_w;
    for (int j = tid; j < 1024; j += NTHREADS) {
        float4 v = pwg4[j];
        psm[0][j] = v.x; psm[1][j] = v.y; psm[2][j] = v.z; psm[3][j] = v.w;
        pbsm[j] = post_b[j];
    }
    __syncthreads();

    #pragma unroll 1
    for (int g = 0; g < GROUPS; g++) {
        const int r0 = tile0 + warp * ROWS_PER_WARP + g * 4;
        if (r0 + 3 >= B) continue;

        const float4 zv0 = g_z[r0 + 0];
        const float4 zv1 = g_z[r0 + 1];
        const float4 zv2 = g_z[r0 + 2];
        const float4 zv3 = g_z[r0 + 3];

        float4* o0 = (float4*)(out + (size_t)r0 * 1024);
        #pragma unroll
        for (int jt = 0; jt < 8; jt++) {
            const int fi = jt * 32 + lane;
            float4 w0 = ((const float4*)psm[0])[fi];
            float4 w1 = ((const float4*)psm[1])[fi];
            float4 w2 = ((const float4*)psm[2])[fi];
            float4 w3 = ((const float4*)psm[3])[fi];
            float4 bb = ((const float4*)pbsm)[fi];
            float4 o;
            o.x = bb.x + zv0.x*w0.x + zv0.y*w1.x + zv0.z*w2.x + zv0.w*w3.x;
            o.y = bb.y + zv0.x*w0.y + zv0.y*w1.y + zv0.z*w2.y + zv0.w*w3.y;
            o.z = bb.z + zv0.x*w0.z + zv0.y*w1.z + zv0.z*w2.z + zv0.w*w3.z;
            o.w = bb.w + zv0.x*w0.w + zv0.y*w1.w + zv0.z*w2.w + zv0.w*w3.w;
            __stcs(&o0[fi], o);
            o.x = bb.x + zv1.x*w0.x + zv1.y*w1.x + zv1.z*w2.x + zv1.w*w3.x;
            o.y = bb.y + zv1.x*w0.y + zv1.y*w1.y + zv1.z*w2.y + zv1.w*w3.y;
            o.z = bb.z + zv1.x*w0.z + zv1.y*w1.z + zv1.z*w2.z + zv1.w*w3.z;
            o.w = bb.w + zv1.x*w0.w + zv1.y*w1.w + zv1.z*w2.w + zv1.w*w3.w;
            __stcs(&o0[256 + fi], o);
            o.x = bb.x + zv2.x*w0.x + zv2.y*w1.x + zv2.z*w2.x + zv2.w*w3.x;
            o.y = bb.y + zv2.x*w0.y + zv2.y*w1.y + zv2.z*w2.y + zv2.w*w3.y;
            o.z = bb.z + zv2.x*w0.z + zv2.y*w1.z + zv2.z*w2.z + zv2.w*w3.z;
            o.w = bb.w + zv2.x*w0.w + zv2.y*w1.w + zv2.z*w2.w + zv2.w*w3.w;
            __stcs(&o0[512 + fi], o);
            o.x = bb.x + zv3.x*w0.x + zv3.y*w1.x + zv3.z*w2.x + zv3.w*w3.x;
            o.y = bb.y + zv3.x*w0.y + zv3.y*w1.y + zv3.z*w2.y + zv3.w*w3.y;
            o.z = bb.z + zv3.x*w0.z + zv3.y*w1.z + zv3.z*w2.z + zv3.w*w3.z;
            o.w = bb.w + zv3.x*w0.w + zv3.y*w1.w + zv3.z*w2.w + zv3.w*w3.w;
            __stcs(&o0[768 + fi], o);
        }
    }
}

extern "C" void kernel_launch(void* const* d_in, const int* in_sizes, int n_in,
                              void* d_out, int out_size) {
    const float* x      = (const float*)d_in[0];
    const float* pre_w  = (const float*)d_in[1];
    const float* pre_b  = (const float*)d_in[2];
    const float* qw     = (const float*)d_in[3];
    const float* post_w = (const float*)d_in[4];
    const float* post_b = (const float*)d_in[5];
    float* out = (float*)d_out;

    int B = in_sizes[0] / 1024;
    if (B > BMAX) B = BMAX;

    const int blocksA = (B + TILE - 1) / TILE;
    dots_kernel<<<blocksA, NTHREADS>>>(x, pre_w, B);

    const int blocksC = (B + NTHREADS - 1) / NTHREADS;
    circuit_kernel<<<blocksC, NTHREADS>>>(pre_b, qw, B);

    const int blocksB = (B + TILE - 1) / TILE;
    post_kernel<<<blocksB, NTHREADS>>>(post_w, post_b, out, B);
}

// round 4
// speedup vs baseline: 1.1694x; 1.0005x over previous
#include <cuda_runtime.h>

#define TILE 64
#define NTHREADS 256
#define WARPS 8
#define ROWS_PER_WARP (TILE / WARPS)   // 8
#define GROUPS (ROWS_PER_WARP / 4)     // 2
#define PI_F 3.14159265358979323846f
#define RSQRT2 0.70710678118654752440f

__global__ __launch_bounds__(NTHREADS, 5) void qp_kernel(
    const float* __restrict__ x,       // [B,1024]
    const float* __restrict__ pre_w,   // [4,1024]
    const float* __restrict__ pre_b,   // [4]
    const float* __restrict__ qw,      // [1,4,3]
    const float* __restrict__ post_w,  // [1024,4]
    const float* __restrict__ post_b,  // [1024]
    float* __restrict__ out,           // [B,1024]
    int B)
{
    __shared__ float wsm[4][1024];     // pre_w, q-major
    __shared__ float psm[4][1024];     // post_w SoA
    __shared__ float pbsm[1024];       // post_b
    __shared__ float usm[4][8];        // Rot gate matrices (uniform)

    const int tid  = threadIdx.x;
    const int warp = tid >> 5;
    const int lane = tid & 31;
    const int tile0 = blockIdx.x * TILE;
    const unsigned FULL = 0xffffffffu;

    // ---------------- stage weights into SMEM (once per block) -----------
    for (int i = tid; i < 4096; i += NTHREADS)
        ((float*)wsm)[i] = pre_w[i];
    const float4* pwg4 = (const float4*)post_w;
    for (int j = tid; j < 1024; j += NTHREADS) {
        float4 v = pwg4[j];
        psm[0][j] = v.x; psm[1][j] = v.y; psm[2][j] = v.z; psm[3][j] = v.w;
        pbsm[j] = post_b[j];
    }
    if (tid < 4) {
        float phi = qw[tid * 3 + 0];
        float th  = qw[tid * 3 + 1];
        float om  = qw[tid * 3 + 2];
        float spo, cpo, spm, cpm, st, ct;
        sincosf(0.5f * (phi + om), &spo, &cpo);
        sincosf(0.5f * (phi - om), &spm, &cpm);
        sincosf(0.5f * th,         &st,  &ct);
        usm[tid][0] =  cpo * ct;  usm[tid][1] = -spo * ct;  // u00
        usm[tid][2] = -cpm * st;  usm[tid][3] = -spm * st;  // u01
        usm[tid][4] =  cpm * st;  usm[tid][5] = -spm * st;  // u10
        usm[tid][6] =  cpo * ct;  usm[tid][7] =  spo * ct;  // u11
    }
    __syncthreads();

    // ---------------- warp-autonomous loop over 4-row groups -------------
    #pragma unroll 1
    for (int g = 0; g < GROUPS; g++) {
        const int r0 = tile0 + warp * ROWS_PER_WARP + g * 4;
        if (r0 + 3 >= B) continue;

        // ===== dots: acc[r*4+q] partial per lane =====
        const float4* xr0 = (const float4*)(x + (size_t)r0 * 1024);
        float v[16];
        #pragma unroll
        for (int i = 0; i < 16; i++) v[i] = 0.0f;

        #pragma unroll
        for (int it = 0; it < 8; it++) {
            const int idx = it * 32 + lane;
            float4 w0 = ((const float4*)wsm[0])[idx];
            float4 w1 = ((const float4*)wsm[1])[idx];
            float4 w2 = ((const float4*)wsm[2])[idx];
            float4 w3 = ((const float4*)wsm[3])[idx];
            #pragma unroll
            for (int r = 0; r < 4; r++) {
                float4 xv = __ldcs(&xr0[(size_t)r * 256 + idx]);
                v[r*4+0] += xv.x*w0.x + xv.y*w0.y + xv.z*w0.z + xv.w*w0.w;
                v[r*4+1] += xv.x*w1.x + xv.y*w1.y + xv.z*w1.z + xv.w*w1.w;
                v[r*4+2] += xv.x*w2.x + xv.y*w2.y + xv.z*w2.z + xv.w*w2.w;
                v[r*4+3] += xv.x*w3.x + xv.y*w3.y + xv.z*w3.z + xv.w*w3.w;
            }
        }

        // ===== distributing reduce: 16 shfls; S[idx] lands on lanes 2*idx, 2*idx+1
        #pragma unroll
        for (int i = 0; i < 8; i++) {
            float send = (lane & 16) ? v[i] : v[i+8];
            float recv = __shfl_xor_sync(FULL, send, 16);
            v[i] = ((lane & 16) ? v[i+8] : v[i]) + recv;
        }
        #pragma unroll
        for (int i = 0; i < 4; i++) {
            float send = (lane & 8) ? v[i] : v[i+4];
            float recv = __shfl_xor_sync(FULL, send, 8);
            v[i] = ((lane & 8) ? v[i+4] : v[i]) + recv;
        }
        #pragma unroll
        for (int i = 0; i < 2; i++) {
            float send = (lane & 4) ? v[i] : v[i+2];
            float recv = __shfl_xor_sync(FULL, send, 4);
            v[i] = ((lane & 4) ? v[i+2] : v[i]) + recv;
        }
        {
            float send = (lane & 2) ? v[0] : v[1];
            float recv = __shfl_xor_sync(FULL, send, 2);
            v[0] = ((lane & 2) ? v[1] : v[0]) + recv;
        }
        v[0] += __shfl_xor_sync(FULL, v[0], 1);
        // lane l holds S[(l>>1)&15], S[r*4+q] at lane 2*(r*4+q)

        // ===== per-(row,qubit) single-qubit states on 16 lanes ==========
        // lane k (k = lane&15): r = k>>2, q = k&3
        const int k  = lane & 15;
        const int qk = k & 3;
        float sval = __shfl_sync(FULL, v[0], k << 1);
        float f = tanhf(sval + __ldg(&pre_b[qk])) * PI_F;
        float sa, ca; sincosf(0.5f * atanf(f), &sa, &ca);
        float sb, cb; sincosf(0.5f * atanf(f * f), &sb, &cb);
        float Am = (ca - sa) * RSQRT2;
        float Bm = (ca + sa) * RSQRT2;
        float v0r = Am * cb, v0i = -Am * sb;
        float v1r = Bm * cb, v1i =  Bm * sb;

        // ===== circuit: two passes, 16 lanes = 16 amplitudes of one row ==
        const int j = lane & 15;
        float zp[2][4];
        #pragma unroll
        for (int p = 0; p < 2; p++) {
            const int rr = (p << 1) | (lane >> 4);   // row within group
            float ar, ai;
            #pragma unroll
            for (int q = 0; q < 4; q++) {
                const int src = (rr << 2) | q;
                float f0r = __shfl_sync(FULL, v0r, src);
                float f0i = __shfl_sync(FULL, v0i, src);
                float f1r = __shfl_sync(FULL, v1r, src);
                float f1i = __shfl_sync(FULL, v1i, src);
                const int bq = (j >> (3 - q)) & 1;
                float wr_ = bq ? f1r : f0r;
                float wi_ = bq ? f1i : f0i;
                if (q == 0) { ar = wr_; ai = wi_; }
                else {
                    float nr = ar*wr_ - ai*wi_;
                    ai = ar*wi_ + ai*wr_;
                    ar = nr;
                }
            }
            // CNOT ring: composed gather permutation
            int jg = j;
            jg ^= (jg & 1) << 3;
            jg ^= (jg >> 1) & 1;
            jg ^= ((jg >> 2) & 1) << 1;
            jg ^= ((jg >> 3) & 1) << 2;
            const int srcp = (lane & 16) | jg;
            float nar = __shfl_sync(FULL, ar, srcp);
            float nai = __shfl_sync(FULL, ai, srcp);
            ar = nar; ai = nai;
            // Rot gates via shfl_xor butterflies
            #pragma unroll
            for (int q = 0; q < 4; q++) {
                const int m = 8 >> q;
                float pr_ = __shfl_xor_sync(FULL, ar, m);
                float pi_ = __shfl_xor_sync(FULL, ai, m);
                const bool bit = (j & m) != 0;
                float fr = bit ? usm[q][4] : usm[q][0];
                float fi = bit ? usm[q][5] : usm[q][1];
                float gr = bit ? usm[q][6] : usm[q][2];
                float gi = bit ? usm[q][7] : usm[q][3];
                float xr = bit ? pr_ : ar, xi = bit ? pi_ : ai;
                float yr = bit ? ar : pr_, yi = bit ? ai : pi_;
                float nr = fr*xr - fi*xi + gr*yr - gi*yi;
                float ni = fr*xi + fi*xr + gr*yi + gi*yr;
                ar = nr; ai = ni;
            }
            // readout + 16-lane butterfly per z_q
            float prob = ar*ar + ai*ai;
            float z0 = (j & 8) ? -prob : prob;
            float z1 = (j & 4) ? -prob : prob;
            float z2 = (j & 2) ? -prob : prob;
            float z3 = (j & 1) ? -prob : prob;
            #pragma unroll
            for (int off = 8; off > 0; off >>= 1) {
                z0 += __shfl_xor_sync(FULL, z0, off);
                z1 += __shfl_xor_sync(FULL, z1, off);
                z2 += __shfl_xor_sync(FULL, z2, off);
                z3 += __shfl_xor_sync(FULL, z3, off);
            }
            zp[p][0] = z0; zp[p][1] = z1; zp[p][2] = z2; zp[p][3] = z3;
        }

        // broadcast z-vectors: row0=pass0/lane0, row1=pass0/lane16, ...
        float4 zv0, zv1, zv2, zv3;
        zv0.x = __shfl_sync(FULL, zp[0][0], 0);
        zv0.y = __shfl_sync(FULL, zp[0][1], 0);
        zv0.z = __shfl_sync(FULL, zp[0][2], 0);
        zv0.w = __shfl_sync(FULL, zp[0][3], 0);
        zv1.x = __shfl_sync(FULL, zp[0][0], 16);
        zv1.y = __shfl_sync(FULL, zp[0][1], 16);
        zv1.z = __shfl_sync(FULL, zp[0][2], 16);
        zv1.w = __shfl_sync(FULL, zp[0][3], 16);
        zv2.x = __shfl_sync(FULL, zp[1][0], 0);
        zv2.y = __shfl_sync(FULL, zp[1][1], 0);
        zv2.z = __shfl_sync(FULL, zp[1][2], 0);
        zv2.w = __shfl_sync(FULL, zp[1][3], 0);
        zv3.x = __shfl_sync(FULL, zp[1][0], 16);
        zv3.y = __shfl_sync(FULL, zp[1][1], 16);
        zv3.z = __shfl_sync(FULL, zp[1][2], 16);
        zv3.w = __shfl_sync(FULL, zp[1][3], 16);

        // ===== stores: out[r] = z[r] @ post_w^T + post_b =====
        float4* o0 = (float4*)(out + (size_t)r0 * 1024);
        #pragma unroll
        for (int jt = 0; jt < 8; jt++) {
            const int fi = jt * 32 + lane;
            float4 w0 = ((const float4*)psm[0])[fi];
            float4 w1 = ((const float4*)psm[1])[fi];
            float4 w2 = ((const float4*)psm[2])[fi];
            float4 w3 = ((const float4*)psm[3])[fi];
            float4 bb = ((const float4*)pbsm)[fi];
            float4 o;
            o.x = bb.x + zv0.x*w0.x + zv0.y*w1.x + zv0.z*w2.x + zv0.w*w3.x;
            o.y = bb.y + zv0.x*w0.y + zv0.y*w1.y + zv0.z*w2.y + zv0.w*w3.y;
            o.z = bb.z + zv0.x*w0.z + zv0.y*w1.z + zv0.z*w2.z + zv0.w*w3.z;
            o.w = bb.w + zv0.x*w0.w + zv0.y*w1.w + zv0.z*w2.w + zv0.w*w3.w;
            __stcs(&o0[fi], o);
            o.x = bb.x + zv1.x*w0.x + zv1.y*w1.x + zv1.z*w2.x + zv1.w*w3.x;
            o.y = bb.y + zv1.x*w0.y + zv1.y*w1.y + zv1.z*w2.y + zv1.w*w3.y;
            o.z = bb.z + zv1.x*w0.z + zv1.y*w1.z + zv1.z*w2.z + zv1.w*w3.z;
            o.w = bb.w + zv1.x*w0.w + zv1.y*w1.w + zv1.z*w2.w + zv1.w*w3.w;
            __stcs(&o0[256 + fi], o);
            o.x = bb.x + zv2.x*w0.x + zv2.y*w1.x + zv2.z*w2.x + zv2.w*w3.x;
            o.y = bb.y + zv2.x*w0.y + zv2.y*w1.y + zv2.z*w2.y + zv2.w*w3.y;
            o.z = bb.z + zv2.x*w0.z + zv2.y*w1.z + zv2.z*w2.z + zv2.w*w3.z;
            o.w = bb.w + zv2.x*w0.w + zv2.y*w1.w + zv2.z*w2.w + zv2.w*w3.w;
            __stcs(&o0[512 + fi], o);
            o.x = bb.x + zv3.x*w0.x + zv3.y*w1.x + zv3.z*w2.x + zv3.w*w3.x;
            o.y = bb.y + zv3.x*w0.y + zv3.y*w1.y + zv3.z*w2.y + zv3.w*w3.y;
            o.z = bb.z + zv3.x*w0.z + zv3.y*w1.z + zv3.z*w2.z + zv3.w*w3.z;
            o.w = bb.w + zv3.x*w0.w + zv3.y*w1.w + zv3.z*w2.w + zv3.w*w3.w;
            __stcs(&o0[768 + fi], o);
        }
    }
}

extern "C" void kernel_launch(void* const* d_in, const int* in_sizes, int n_in,
                              void* d_out, int out_size) {
    const float* x      = (const float*)d_in[0];
    const float* pre_w  = (const float*)d_in[1];
    const float* pre_b  = (const float*)d_in[2];
    const float* qw     = (const float*)d_in[3];
    const float* post_w = (const float*)d_in[4];
    const float* post_b = (const float*)d_in[5];
    float* out = (float*)d_out;

    const int B = in_sizes[0] / 1024;
    const int blocks = (B + TILE - 1) / TILE;
    qp_kernel<<<blocks, NTHREADS>>>(x, pre_w, pre_b, qw, post_w, post_b, out, B);
}

// round 5
// speedup vs baseline: 1.3322x; 1.1392x over previous
#include <cuda_runtime.h>

#define TILE 128
#define NTHREADS 256
#define WARPS 8
#define ROWS_PER_WARP (TILE / WARPS)   // 16
#define GROUPS (ROWS_PER_WARP / 8)     // 2 groups of 8 rows
#define PI_F 3.14159265358979323846f
#define RSQRT2 0.70710678118654752440f

__global__ __launch_bounds__(NTHREADS, 4) void qp_kernel(
    const float* __restrict__ x,       // [B,1024]
    const float* __restrict__ pre_w,   // [4,1024]
    const float* __restrict__ pre_b,   // [4]
    const float* __restrict__ qw,      // [1,4,3]
    const float* __restrict__ post_w,  // [1024,4]
    const float* __restrict__ post_b,  // [1024]
    float* __restrict__ out,           // [B,1024]
    int B)
{
    __shared__ float wsm[4][1024];     // pre_w, q-major (16KB)
    __shared__ float psm[4][1024];     // post_w SoA (16KB)
    __shared__ float pbsm[1024];       // post_b (4KB)
    __shared__ float hsm[TILE][4];     // angles (2KB)
    __shared__ float4 zsm[TILE];       // expectations (2KB)
    __shared__ float usm[4][8];        // Rot matrices
    __shared__ float prebias[4];

    const int tid  = threadIdx.x;
    const int warp = tid >> 5;
    const int lane = tid & 31;
    const int tile0 = blockIdx.x * TILE;
    const unsigned FULL = 0xffffffffu;

    // ---------------- stage weights ----------------
    for (int i = tid; i < 4096; i += NTHREADS)
        ((float*)wsm)[i] = pre_w[i];
    const float4* pwg4 = (const float4*)post_w;
    for (int j = tid; j < 1024; j += NTHREADS) {
        float4 v = pwg4[j];
        psm[0][j] = v.x; psm[1][j] = v.y; psm[2][j] = v.z; psm[3][j] = v.w;
        pbsm[j] = post_b[j];
    }
    if (tid < 4) {
        prebias[tid] = pre_b[tid];
        float phi = qw[tid * 3 + 0];
        float th  = qw[tid * 3 + 1];
        float om  = qw[tid * 3 + 2];
        float spo, cpo, spm, cpm, st, ct;
        sincosf(0.5f * (phi + om), &spo, &cpo);
        sincosf(0.5f * (phi - om), &spm, &cpm);
        sincosf(0.5f * th,         &st,  &ct);
        usm[tid][0] =  cpo * ct;  usm[tid][1] = -spo * ct;  // u00
        usm[tid][2] = -cpm * st;  usm[tid][3] = -spm * st;  // u01
        usm[tid][4] =  cpm * st;  usm[tid][5] = -spm * st;  // u10
        usm[tid][6] =  cpo * ct;  usm[tid][7] =  spo * ct;  // u11
    }
    __syncthreads();

    // ---------------- Phase 1: dots, 8 rows per group ----------------
    #pragma unroll 1
    for (int g = 0; g < GROUPS; g++) {
        const int lr0 = warp * ROWS_PER_WARP + g * 8;
        const int r0  = tile0 + lr0;
        if (r0 + 7 >= B) continue;

        const float4* xr0 = (const float4*)(x + (size_t)r0 * 1024);
        float v[32];                  // v[r*4+q]
        #pragma unroll
        for (int i = 0; i < 32; i++) v[i] = 0.0f;

        #pragma unroll
        for (int it = 0; it < 8; it++) {
            const int idx = it * 32 + lane;
            float4 w0 = ((const float4*)wsm[0])[idx];
            float4 w1 = ((const float4*)wsm[1])[idx];
            float4 w2 = ((const float4*)wsm[2])[idx];
            float4 w3 = ((const float4*)wsm[3])[idx];
            #pragma unroll
            for (int r = 0; r < 8; r++) {
                float4 xv = __ldcs(&xr0[(size_t)r * 256 + idx]);
                v[r*4+0] += xv.x*w0.x + xv.y*w0.y + xv.z*w0.z + xv.w*w0.w;
                v[r*4+1] += xv.x*w1.x + xv.y*w1.y + xv.z*w1.z + xv.w*w1.w;
                v[r*4+2] += xv.x*w2.x + xv.y*w2.y + xv.z*w2.z + xv.w*w2.w;
                v[r*4+3] += xv.x*w3.x + xv.y*w3.y + xv.z*w3.z + xv.w*w3.w;
            }
        }

        // distributing reduce: 31 shfls, lane l ends holding S[l]=v_l summed
        #pragma unroll
        for (int i = 0; i < 16; i++) {
            float send = (lane & 16) ? v[i] : v[i+16];
            float recv = __shfl_xor_sync(FULL, send, 16);
            v[i] = ((lane & 16) ? v[i+16] : v[i]) + recv;
        }
        #pragma unroll
        for (int i = 0; i < 8; i++) {
            float send = (lane & 8) ? v[i] : v[i+8];
            float recv = __shfl_xor_sync(FULL, send, 8);
            v[i] = ((lane & 8) ? v[i+8] : v[i]) + recv;
        }
        #pragma unroll
        for (int i = 0; i < 4; i++) {
            float send = (lane & 4) ? v[i] : v[i+4];
            float recv = __shfl_xor_sync(FULL, send, 4);
            v[i] = ((lane & 4) ? v[i+4] : v[i]) + recv;
        }
        #pragma unroll
        for (int i = 0; i < 2; i++) {
            float send = (lane & 2) ? v[i] : v[i+2];
            float recv = __shfl_xor_sync(FULL, send, 2);
            v[i] = ((lane & 2) ? v[i+2] : v[i]) + recv;
        }
        {
            float send = (lane & 1) ? v[0] : v[1];
            float recv = __shfl_xor_sync(FULL, send, 1);
            v[0] = ((lane & 1) ? v[1] : v[0]) + recv;
        }
        // lane l: S for row lr0+(l>>2), qubit l&3
        const int q = lane & 3;
        hsm[lr0 + (lane >> 2)][q] = tanhf(v[0] + prebias[q]) * PI_F;
    }
    __syncthreads();

    // ---------------- Phase 2: circuit, thread-per-row ----------------
    if (tid < TILE && (tile0 + tid) < B) {
        float4 hv = *(const float4*)hsm[tid];
        float hq[4] = {hv.x, hv.y, hv.z, hv.w};

        float vr[4][2], vi[4][2];
        #pragma unroll
        for (int qq = 0; qq < 4; qq++) {
            float f = hq[qq];
            float sa, ca; sincosf(0.5f * atanf(f), &sa, &ca);
            float A  = (ca - sa) * RSQRT2;
            float Bv = (ca + sa) * RSQRT2;
            float sb, cb; sincosf(0.5f * atanf(f * f), &sb, &cb);
            vr[qq][0] = A  * cb;  vi[qq][0] = -A  * sb;
            vr[qq][1] = Bv * cb;  vi[qq][1] =  Bv * sb;
        }
        float c2r[4], c2i[4];
        #pragma unroll
        for (int j = 0; j < 4; j++) {
            int b3 = (j >> 1) & 1, b2 = j & 1;
            c2r[j] = vr[0][b3]*vr[1][b2] - vi[0][b3]*vi[1][b2];
            c2i[j] = vr[0][b3]*vi[1][b2] + vi[0][b3]*vr[1][b2];
        }
        float c3r[8], c3i[8];
        #pragma unroll
        for (int j = 0; j < 8; j++) {
            int hi = j >> 1, b1 = j & 1;
            c3r[j] = c2r[hi]*vr[2][b1] - c2i[hi]*vi[2][b1];
            c3i[j] = c2r[hi]*vi[2][b1] + c2i[hi]*vr[2][b1];
        }
        float pr[16], pim[16];
        #pragma unroll
        for (int j = 0; j < 16; j++) {
            int hi = j >> 1, b0 = j & 1;
            pr[j]  = c3r[hi]*vr[3][b0] - c3i[hi]*vi[3][b0];
            pim[j] = c3r[hi]*vi[3][b0] + c3i[hi]*vr[3][b0];
        }
        float tr[16], ti[16];
        #pragma unroll
        for (int j = 0; j < 16; j++) {
            int xg = j;
            xg ^= (xg & 1) << 3;
            xg ^= (xg >> 1) & 1;
            xg ^= ((xg >> 2) & 1) << 1;
            xg ^= ((xg >> 3) & 1) << 2;
            tr[j] = pr[xg];
            ti[j] = pim[xg];
        }
        #pragma unroll
        for (int qq = 0; qq < 4; qq++) {
            const float u00r = usm[qq][0], u00i = usm[qq][1];
            const float u01r = usm[qq][2], u01i = usm[qq][3];
            const float u10r = usm[qq][4], u10i = usm[qq][5];
            const float u11r = usm[qq][6], u11i = usm[qq][7];
            const int mask = 8 >> qq;
            #pragma unroll
            for (int j0 = 0; j0 < 16; j0++) {
                if (j0 & mask) continue;
                const int j1 = j0 | mask;
                float ar = tr[j0], ai = ti[j0];
                float br = tr[j1], bi = ti[j1];
                tr[j0] = u00r*ar - u00i*ai + u01r*br - u01i*bi;
                ti[j0] = u00r*ai + u00i*ar + u01r*bi + u01i*br;
                tr[j1] = u10r*ar - u10i*ai + u11r*br - u11i*bi;
                ti[j1] = u10r*ai + u10i*ar + u11r*bi + u11i*br;
            }
        }
        float z0 = 0.f, z1 = 0.f, z2 = 0.f, z3 = 0.f;
        #pragma unroll
        for (int j = 0; j < 16; j++) {
            float p = tr[j]*tr[j] + ti[j]*ti[j];
            z0 += (j & 8) ? -p : p;
            z1 += (j & 4) ? -p : p;
            z2 += (j & 2) ? -p : p;
            z3 += (j & 1) ? -p : p;
        }
        zsm[tid] = make_float4(z0, z1, z2, z3);
    }
    __syncthreads();

    // ---------------- Phase 3: out = z @ post_w^T + post_b, 8 rows/group --
    #pragma unroll 1
    for (int g = 0; g < GROUPS; g++) {
        const int lr0 = warp * ROWS_PER_WARP + g * 8;
        const int r0  = tile0 + lr0;
        if (r0 + 7 >= B) continue;

        float4 zv[8];
        #pragma unroll
        for (int r = 0; r < 8; r++) zv[r] = zsm[lr0 + r];

        float4* o0 = (float4*)(out + (size_t)r0 * 1024);
        #pragma unroll
        for (int jt = 0; jt < 8; jt++) {
            const int fi = jt * 32 + lane;
            float4 w0 = ((const float4*)psm[0])[fi];
            float4 w1 = ((const float4*)psm[1])[fi];
            float4 w2 = ((const float4*)psm[2])[fi];
            float4 w3 = ((const float4*)psm[3])[fi];
            float4 bb = ((const float4*)pbsm)[fi];
            #pragma unroll
            for (int r = 0; r < 8; r++) {
                float4 o;
                o.x = bb.x + zv[r].x*w0.x + zv[r].y*w1.x + zv[r].z*w2.x + zv[r].w*w3.x;
                o.y = bb.y + zv[r].x*w0.y + zv[r].y*w1.y + zv[r].z*w2.y + zv[r].w*w3.y;
                o.z = bb.z + zv[r].x*w0.z + zv[r].y*w1.z + zv[r].z*w2.z + zv[r].w*w3.z;
                o.w = bb.w + zv[r].x*w0.w + zv[r].y*w1.w + zv[r].z*w2.w + zv[r].w*w3.w;
                __stcs(&o0[(size_t)r * 256 + fi], o);
            }
        }
    }
}

extern "C" void kernel_launch(void* const* d_in, const int* in_sizes, int n_in,
                              void* d_out, int out_size) {
    const float* x      = (const float*)d_in[0];
    const float* pre_w  = (const float*)d_in[1];
    const float* pre_b  = (const float*)d_in[2];
    const float* qw     = (const float*)d_in[3];
    const float* post_w = (const float*)d_in[4];
    const float* post_b = (const float*)d_in[5];
    float* out = (float*)d_out;

    const int B = in_sizes[0] / 1024;
    const int blocks = (B + TILE - 1) / TILE;
    qp_kernel<<<blocks, NTHREADS>>>(x, pre_w, pre_b, qw, post_w, post_b, out, B);
}